// round 15
// baseline (speedup 1.0000x reference)
#include <cuda_runtime.h>
#include <math.h>

#define B_    2
#define S_    2048
#define E_    8
#define HID_  768
#define NH_   12
#define HD_   64
#define L_    2056           // E + S
#define M_ROWS 4112          // B * L
#define M_PAD  4224          // 33 * 128 (padded rows for prepacked X)
#define WPR   66             // mask words per q-row
#define NEG_  (-10000.0f)

// -ln(10000)/64 in fp32
#define RC_ (-1.4391157031059265e-01f)

// ---------------- scratch ----------------
__device__ __align__(16) float    g_qr[B_ * NH_ * S_ * HD_];   // [b][h][s][d], 1/8-scaled, tf32-rounded
__device__ __align__(16) float    g_kt[B_ * NH_ * HD_ * L_];   // [b][h][d][pos], tf32-rounded
__device__ __align__(16) float    g_v [B_ * NH_ * L_ * HD_];   // [b][h][pos][d], tf32-rounded
__device__           unsigned     g_mask[B_ * S_ * WPR];       // packed enh bits
__device__ __align__(16) float    g_xr[M_PAD * HID_];          // prepacked tf32-rounded X rows
__device__ __align__(16) float    g_wr[2 * HID_ * HID_];       // prepacked tf32-rounded W
__device__ __align__(8)  float    g_sv[L_ * 32];               // sinvec[pos][j]
__device__ __align__(8)  float    g_cv[L_ * 32];               // cosvec[pos][j]

// ---------------- helpers ----------------
__device__ __forceinline__ float tf32r(float x) {
    unsigned u;
    asm("cvt.rna.tf32.f32 %0, %1;" : "=r"(u) : "f"(x));
    return __uint_as_float(u);
}

__device__ __forceinline__ void mma_tf32(float* d,
                                         unsigned a0, unsigned a1, unsigned a2, unsigned a3,
                                         unsigned b0, unsigned b1) {
    asm volatile(
        "mma.sync.aligned.m16n8k8.row.col.f32.tf32.tf32.f32 "
        "{%0,%1,%2,%3}, {%4,%5,%6,%7}, {%8,%9}, {%0,%1,%2,%3};"
        : "+f"(d[0]), "+f"(d[1]), "+f"(d[2]), "+f"(d[3])
        : "r"(a0), "r"(a1), "r"(a2), "r"(a3), "r"(b0), "r"(b1));
}

__device__ __forceinline__ void cpa16(unsigned dst, const void* src, unsigned sz) {
    asm volatile("cp.async.cg.shared.global [%0], [%1], 16, %2;"
                 :: "r"(dst), "l"(src), "r"(sz));
}
__device__ __forceinline__ void cpa16u(unsigned dst, const void* src) {
    asm volatile("cp.async.cg.shared.global [%0], [%1], 16;"
                 :: "r"(dst), "l"(src));
}

// ---------------- kernel 0a: rope table ----------------
__global__ void rope_table_kernel() {
    int idx = blockIdx.x * blockDim.x + threadIdx.x;
    if (idx >= L_ * 32) return;
    int j = idx & 31;
    int pos = idx >> 5;
    int i = j >> 1;
    float da = expf((float)(2 * i) * RC_);
    float db = expf((float)(2 * (16 + i)) * RC_);
    float aa = (float)pos * da, ab = (float)pos * db;
    g_sv[idx] = (j & 1) ? cosf(aa) : sinf(aa);
    g_cv[idx] = (j & 1) ? cosf(ab) : sinf(ab);
}

// ---------------- kernel 0b: prepack X (merged, padded) and W, tf32-rounded ----------------
__global__ void prepack_kernel(const float* __restrict__ embx, const float* __restrict__ kvh,
                               const float* __restrict__ W) {
    const int XN = M_PAD * (HID_ / 4);            // float4 count for X
    const int WN = 2 * HID_ * (HID_ / 4);
    int idx = blockIdx.x * blockDim.x + threadIdx.x;
    if (idx < XN) {
        int m = idx / (HID_ / 4);
        int c4 = (idx % (HID_ / 4)) * 4;
        float4 v = make_float4(0.f, 0.f, 0.f, 0.f);
        if (m < M_ROWS) {
            int b = m / L_, pos = m % L_;
            const float* src = (pos < E_) ? embx + ((size_t)(b * E_ + pos)) * HID_
                                          : kvh  + ((size_t)(b * S_ + (pos - E_))) * HID_;
            v = *(const float4*)(src + c4);
        }
        v.x = tf32r(v.x); v.y = tf32r(v.y); v.z = tf32r(v.z); v.w = tf32r(v.w);
        *(float4*)&g_xr[(size_t)m * HID_ + c4] = v;
    } else if (idx < XN + WN) {
        int k = idx - XN;
        float4 v = *(const float4*)(W + (size_t)k * 4);
        v.x = tf32r(v.x); v.y = tf32r(v.y); v.z = tf32r(v.z); v.w = tf32r(v.w);
        *(float4*)&g_wr[(size_t)k * 4] = v;
    }
}

// ---------------- kernel 1: mask pack ----------------
__global__ void mask_kernel(const float* __restrict__ ru) {
    int gw = (blockIdx.x * blockDim.x + threadIdx.x) >> 5;
    int lane = threadIdx.x & 31;
    if (gw >= B_ * S_ * WPR) return;
    int w = gw % WPR;
    int q = (gw / WPR) % S_;
    int b = gw / (WPR * S_);
    int j = w * 32 + lane;
    bool ok = false;
    if (j < L_) {
        if (j < E_) ok = true;
        else {
            int si = j - E_;
            ok = (ru[((size_t)b * S_ + q) * S_ + si] >= 0.1f) && (si != q);
        }
    }
    unsigned bits = __ballot_sync(0xffffffffu, ok);
    if (lane == 0) g_mask[gw] = bits;
}

// ---------------- kernel 2: Q rope (table lookup) ----------------
__global__ void qrope_kernel(const float* __restrict__ qhs) {
    int idx = blockIdx.x * blockDim.x + threadIdx.x;
    if (idx >= B_ * S_ * NH_ * 32) return;
    int j = idx & 31;
    int h = (idx >> 5) % NH_;
    int s = (idx / (32 * NH_)) % S_;
    int b = idx / (32 * NH_ * S_);
    const float* src = qhs + ((size_t)(b * S_ + s)) * HID_ + h * HD_ + 2 * j;
    float x0 = src[0], x1 = src[1];
    float sv = g_sv[s * 32 + j];
    float cv = g_cv[s * 32 + j];
    float o0 = -x1 * cv * 0.125f;
    float o1 =  x0 * sv * 0.125f;
    float* dst = g_qr + ((size_t)(b * NH_ + h) * S_ + s) * HD_ + 2 * j;
    dst[0] = tf32r(o0);
    dst[1] = tf32r(o1);
}

// ---------------- kernel 3: tf32 KV GEMM, cp.async double-buffered ----------------
#define GSTR 36
#define ABUF (128 * GSTR)                 // floats per buffer (4608)
__global__ __launch_bounds__(256, 2) void kv_gemm_tc(const float* __restrict__ bias) {
    __shared__ float As[2 * ABUF];
    __shared__ float Ws[2 * ABUF];
    unsigned sbA = (unsigned)__cvta_generic_to_shared(As);
    unsigned sbW = (unsigned)__cvta_generic_to_shared(Ws);
    int nb = blockIdx.x;
    int mt = blockIdx.y;
    int tid = threadIdx.x;
    int warp = tid >> 5, lane = tid & 31;
    int wm = warp >> 2, wn = warp & 3;
    int gid = lane >> 2, tig = lane & 3;

    float acc[4][4][4];
#pragma unroll
    for (int mi = 0; mi < 4; mi++)
#pragma unroll
        for (int ni = 0; ni < 4; ni++)
#pragma unroll
            for (int k = 0; k < 4; k++) acc[mi][ni][k] = 0.f;

    int lr  = tid >> 3;                  // 0..31 row group
    int lk4 = (tid & 7) << 2;            // float offset within 32-chunk (0,4,..,28)
    const float* xbase = g_xr + (size_t)(mt * 128) * HID_;   // rows always valid (padded)
    const float* wbase = g_wr + (size_t)(nb * 128) * HID_;

    // prefetch chunk 0 into buffer 0
#pragma unroll
    for (int it = 0; it < 4; it++) {
        int r = lr + it * 32;
        cpa16u(sbA + (r * GSTR + lk4) * 4, xbase + (size_t)r * HID_ + lk4);
        cpa16u(sbW + (r * GSTR + lk4) * 4, wbase + (size_t)r * HID_ + lk4);
    }
    asm volatile("cp.async.commit_group;");

    for (int c = 0; c < 24; c++) {
        int cur = c & 1;
        if (c + 1 < 24) {
            int nxt = (c + 1) & 1;
            int k0 = (c + 1) * 32;
#pragma unroll
            for (int it = 0; it < 4; it++) {
                int r = lr + it * 32;
                cpa16u(sbA + (nxt * ABUF + r * GSTR + lk4) * 4, xbase + (size_t)r * HID_ + k0 + lk4);
                cpa16u(sbW + (nxt * ABUF + r * GSTR + lk4) * 4, wbase + (size_t)r * HID_ + k0 + lk4);
            }
            asm volatile("cp.async.commit_group;");
            asm volatile("cp.async.wait_group 1;");
        } else {
            asm volatile("cp.async.wait_group 0;");
        }
        __syncthreads();

        const float* Ab = As + cur * ABUF;
        const float* Wb = Ws + cur * ABUF;
#pragma unroll
        for (int kt = 0; kt < 4; kt++) {
            unsigned a[4][4];
#pragma unroll
            for (int mi = 0; mi < 4; mi++) {
                int rA = wm * 64 + mi * 16 + gid;
                a[mi][0] = __float_as_uint(Ab[rA * GSTR + kt * 8 + tig]);
                a[mi][1] = __float_as_uint(Ab[(rA + 8) * GSTR + kt * 8 + tig]);
                a[mi][2] = __float_as_uint(Ab[rA * GSTR + kt * 8 + tig + 4]);
                a[mi][3] = __float_as_uint(Ab[(rA + 8) * GSTR + kt * 8 + tig + 4]);
            }
#pragma unroll
            for (int ni = 0; ni < 4; ni++) {
                int n = wn * 32 + ni * 8 + gid;
                unsigned b0 = __float_as_uint(Wb[n * GSTR + kt * 8 + tig]);
                unsigned b1 = __float_as_uint(Wb[n * GSTR + kt * 8 + tig + 4]);
#pragma unroll
                for (int mi = 0; mi < 4; mi++)
                    mma_tf32(acc[mi][ni], a[mi][0], a[mi][1], a[mi][2], a[mi][3], b0, b1);
            }
        }
        __syncthreads();
    }

    bool isV = (nb >= 6);
#pragma unroll
    for (int ni = 0; ni < 4; ni++) {
        int c = nb * 128 + wn * 32 + ni * 8 + tig * 2;
        float bv0 = bias[c], bv1 = bias[c + 1];
        if (isV) {
            int vcol = c - 768;
            int h = vcol >> 6, d = vcol & 63;
#pragma unroll
            for (int mi = 0; mi < 4; mi++) {
                int mA = mt * 128 + wm * 64 + mi * 16 + gid;
                int mB = mA + 8;
                if (mA < M_ROWS) {
                    int bb = mA / L_, pos = mA % L_;
                    *(float2*)&g_v[(((size_t)(bb * NH_ + h)) * L_ + pos) * HD_ + d] =
                        make_float2(tf32r(acc[mi][ni][0] + bv0), tf32r(acc[mi][ni][1] + bv1));
                }
                if (mB < M_ROWS) {
                    int bb = mB / L_, pos = mB % L_;
                    *(float2*)&g_v[(((size_t)(bb * NH_ + h)) * L_ + pos) * HD_ + d] =
                        make_float2(tf32r(acc[mi][ni][2] + bv0), tf32r(acc[mi][ni][3] + bv1));
                }
            }
        } else {
            int h = c >> 6, d = c & 63;          // d even
            int j = d >> 1;
#pragma unroll
            for (int mi = 0; mi < 4; mi++) {
#pragma unroll
                for (int half = 0; half < 2; half++) {
                    int m = mt * 128 + wm * 64 + mi * 16 + gid + half * 8;
                    if (m >= M_ROWS) continue;
                    int bb = m / L_, pos = m % L_;
                    float sv = g_sv[pos * 32 + j];
                    float cv = g_cv[pos * 32 + j];
                    float x0 = acc[mi][ni][half * 2 + 0] + bv0;
                    float x1 = acc[mi][ni][half * 2 + 1] + bv1;
                    float* base = g_kt + ((size_t)(bb * NH_ + h) * HD_ + d) * L_ + pos;
                    base[0]  = tf32r(-x1 * cv);
                    base[L_] = tf32r( x0 * sv);
                }
            }
        }
    }
}

// ---------------- kernel 4: flash attention (warp-m32, Q in regs, cp.async dbl-buffer) ----------------
#define QP_STR 72
#define KV_STR 72
#define SM_PS  0                       // 128*72 floats (also Q staging)
#define SM_K0  (128 * QP_STR)
#define SM_K1  (SM_K0 + 64 * KV_STR)
#define SM_V0  (SM_K1 + 64 * KV_STR)
#define SM_V1  (SM_V0 + 64 * KV_STR)
#define SM_TOTF (SM_V1 + 64 * KV_STR)  // 27648 floats = 110592 B

__global__ __launch_bounds__(128, 2) void flash_kernel(float* __restrict__ out) {
    extern __shared__ float sm[];
    float* Ps = sm + SM_PS;
    unsigned sbase = (unsigned)__cvta_generic_to_shared(sm);

    int qt = blockIdx.x, h = blockIdx.y, b = blockIdx.z;
    int tid = threadIdx.x;
    int warp = tid >> 5, lane = tid & 31;
    int gid = lane >> 2, tig = lane & 3;
    int wrow = warp * 32;

    const float* ktb = g_kt + (size_t)(b * NH_ + h) * HD_ * L_;
    const float* vb  = g_v  + (size_t)(b * NH_ + h) * L_ * HD_;
    const unsigned* mbg = g_mask + (size_t)(b * S_ + qt * 128) * WPR;

    const float* qbase = g_qr + ((size_t)(b * NH_ + h) * S_ + qt * 128) * HD_;
#pragma unroll
    for (int j = 0; j < 16; j++) {
        int c = lane + j * 32;
        int r = wrow + (c >> 4);
        int cc = (c & 15) << 2;
        float4 v = *(const float4*)(qbase + r * 64 + cc);
        float* q = Ps + r * QP_STR + cc;
        q[0] = v.x; q[1] = v.y; q[2] = v.z; q[3] = v.w;
    }
    __syncwarp();
    unsigned qa[2][8][4];
#pragma unroll
    for (int mi = 0; mi < 2; mi++) {
        int rA = wrow + mi * 16 + gid, rB = rA + 8;
#pragma unroll
        for (int kt = 0; kt < 8; kt++) {
            qa[mi][kt][0] = __float_as_uint(Ps[rA * QP_STR + kt * 8 + tig]);
            qa[mi][kt][1] = __float_as_uint(Ps[rB * QP_STR + kt * 8 + tig]);
            qa[mi][kt][2] = __float_as_uint(Ps[rA * QP_STR + kt * 8 + tig + 4]);
            qa[mi][kt][3] = __float_as_uint(Ps[rB * QP_STR + kt * 8 + tig + 4]);
        }
    }
    __syncwarp();

    float o[2][8][4];
#pragma unroll
    for (int mi = 0; mi < 2; mi++)
#pragma unroll
        for (int nt = 0; nt < 8; nt++)
#pragma unroll
            for (int k = 0; k < 4; k++) o[mi][nt][k] = 0.f;
    float mrow[2][2], lrow[2][2];
#pragma unroll
    for (int mi = 0; mi < 2; mi++) { mrow[mi][0] = mrow[mi][1] = -1e30f; lrow[mi][0] = lrow[mi][1] = 0.f; }

    {
        int pbase = 0;
#pragma unroll
        for (int i = 0; i < 8; i++) {
            int c = tid + i * 128;
            int d = c >> 4, p4 = (c & 15) << 2;
            unsigned dst = sbase + (SM_K0 + d * KV_STR + p4) * 4;
            cpa16(dst, ktb + (size_t)d * L_ + pbase + p4, (pbase + p4 + 4 <= L_) ? 16u : 0u);
        }
#pragma unroll
        for (int i = 0; i < 8; i++) {
            int c = tid + i * 128;
            int pos = c >> 4, d4 = (c & 15) << 2;
            unsigned dst = sbase + (SM_V0 + pos * KV_STR + d4) * 4;
            cpa16(dst, vb + (size_t)(pbase + pos) * HD_ + d4, (pbase + pos < L_) ? 16u : 0u);
        }
        asm volatile("cp.async.commit_group;");
    }

    for (int jt = 0; jt < 33; jt++) {
        int cur = jt & 1;
        asm volatile("cp.async.wait_group 0;");
        __syncthreads();
        if (jt + 1 < 33) {
            int pbase = (jt + 1) * 64;
            int kb = cur ? SM_K0 : SM_K1;
            int vbuf = cur ? SM_V0 : SM_V1;
#pragma unroll
            for (int i = 0; i < 8; i++) {
                int c = tid + i * 128;
                int d = c >> 4, p4 = (c & 15) << 2;
                unsigned dst = sbase + (kb + d * KV_STR + p4) * 4;
                cpa16(dst, ktb + (size_t)d * L_ + pbase + p4, (pbase + p4 + 4 <= L_) ? 16u : 0u);
            }
#pragma unroll
            for (int i = 0; i < 8; i++) {
                int c = tid + i * 128;
                int pos = c >> 4, d4 = (c & 15) << 2;
                unsigned dst = sbase + (vbuf + pos * KV_STR + d4) * 4;
                cpa16(dst, vb + (size_t)(pbase + pos) * HD_ + d4, (pbase + pos < L_) ? 16u : 0u);
            }
            asm volatile("cp.async.commit_group;");
        }

        unsigned mw[2][2][2];
#pragma unroll
        for (int mi = 0; mi < 2; mi++)
#pragma unroll
            for (int hf = 0; hf < 2; hf++) {
                int r = wrow + mi * 16 + gid + hf * 8;
                mw[mi][hf][0] = mbg[(size_t)r * WPR + jt * 2];
                mw[mi][hf][1] = mbg[(size_t)r * WPR + jt * 2 + 1];
            }

        float sf[2][8][4];
#pragma unroll
        for (int mi = 0; mi < 2; mi++)
#pragma unroll
            for (int nt = 0; nt < 8; nt++) {
                unsigned wA = (nt < 4) ? mw[mi][0][0] : mw[mi][0][1];
                unsigned wB = (nt < 4) ? mw[mi][1][0] : mw[mi][1][1];
                int s0 = ((nt & 3) << 3) + (tig << 1);
                sf[mi][nt][0] = ((wA >> s0) & 1u) ? 0.f : NEG_;
                sf[mi][nt][1] = ((wA >> (s0 + 1)) & 1u) ? 0.f : NEG_;
                sf[mi][nt][2] = ((wB >> s0) & 1u) ? 0.f : NEG_;
                sf[mi][nt][3] = ((wB >> (s0 + 1)) & 1u) ? 0.f : NEG_;
            }

        const float* Kb = sm + (cur ? SM_K1 : SM_K0);
#pragma unroll
        for (int kt = 0; kt < 8; kt++) {
#pragma unroll
            for (int nt = 0; nt < 8; nt++) {
                unsigned b0 = __float_as_uint(Kb[(kt * 8 + tig) * KV_STR + nt * 8 + gid]);
                unsigned b1 = __float_as_uint(Kb[(kt * 8 + tig + 4) * KV_STR + nt * 8 + gid]);
                mma_tf32(sf[0][nt], qa[0][kt][0], qa[0][kt][1], qa[0][kt][2], qa[0][kt][3], b0, b1);
                mma_tf32(sf[1][nt], qa[1][kt][0], qa[1][kt][1], qa[1][kt][2], qa[1][kt][3], b0, b1);
            }
        }

#pragma unroll
        for (int mi = 0; mi < 2; mi++) {
            int rA = wrow + mi * 16 + gid, rB = rA + 8;
            float mxA = -1e30f, mxB = -1e30f;
#pragma unroll
            for (int nt = 0; nt < 8; nt++) {
                mxA = fmaxf(mxA, fmaxf(sf[mi][nt][0], sf[mi][nt][1]));
                mxB = fmaxf(mxB, fmaxf(sf[mi][nt][2], sf[mi][nt][3]));
            }
            mxA = fmaxf(mxA, __shfl_xor_sync(0xffffffffu, mxA, 1));
            mxA = fmaxf(mxA, __shfl_xor_sync(0xffffffffu, mxA, 2));
            mxB = fmaxf(mxB, __shfl_xor_sync(0xffffffffu, mxB, 1));
            mxB = fmaxf(mxB, __shfl_xor_sync(0xffffffffu, mxB, 2));
            float mnA = fmaxf(mrow[mi][0], mxA), mnB = fmaxf(mrow[mi][1], mxB);
            float alA = __expf(mrow[mi][0] - mnA), alB = __expf(mrow[mi][1] - mnB);
            float lsA = 0.f, lsB = 0.f;
#pragma unroll
            for (int nt = 0; nt < 8; nt++) {
                float p0 = tf32r(__expf(sf[mi][nt][0] - mnA));
                float p1 = tf32r(__expf(sf[mi][nt][1] - mnA));
                float p2 = tf32r(__expf(sf[mi][nt][2] - mnB));
                float p3 = tf32r(__expf(sf[mi][nt][3] - mnB));
                lsA += p0 + p1; lsB += p2 + p3;
                *(float2*)(Ps + rA * QP_STR + nt * 8 + (tig << 1)) = make_float2(p0, p1);
                *(float2*)(Ps + rB * QP_STR + nt * 8 + (tig << 1)) = make_float2(p2, p3);
            }
            lsA += __shfl_xor_sync(0xffffffffu, lsA, 1);
            lsA += __shfl_xor_sync(0xffffffffu, lsA, 2);
            lsB += __shfl_xor_sync(0xffffffffu, lsB, 1);
            lsB += __shfl_xor_sync(0xffffffffu, lsB, 2);
            lrow[mi][0] = lrow[mi][0] * alA + lsA; mrow[mi][0] = mnA;
            lrow[mi][1] = lrow[mi][1] * alB + lsB; mrow[mi][1] = mnB;
#pragma unroll
            for (int nt = 0; nt < 8; nt++) {
                o[mi][nt][0] *= alA; o[mi][nt][1] *= alA;
                o[mi][nt][2] *= alB; o[mi][nt][3] *= alB;
            }
        }
        __syncwarp();

        const float* Vb = sm + (cur ? SM_V1 : SM_V0);
#pragma unroll
        for (int kt = 0; kt < 8; kt++) {
            unsigned pa[2][4];
#pragma unroll
            for (int mi = 0; mi < 2; mi++) {
                int rA = wrow + mi * 16 + gid, rB = rA + 8;
                pa[mi][0] = __float_as_uint(Ps[rA * QP_STR + kt * 8 + tig]);
                pa[mi][1] = __float_as_uint(Ps[rB * QP_STR + kt * 8 + tig]);
                pa[mi][2] = __float_as_uint(Ps[rA * QP_STR + kt * 8 + tig + 4]);
                pa[mi][3] = __float_as_uint(Ps[rB * QP_STR + kt * 8 + tig + 4]);
            }
#pragma unroll
            for (int nt = 0; nt < 8; nt++) {
                unsigned b0 = __float_as_uint(Vb[(kt * 8 + tig) * KV_STR + nt * 8 + gid]);
                unsigned b1 = __float_as_uint(Vb[(kt * 8 + tig + 4) * KV_STR + nt * 8 + gid]);
                mma_tf32(o[0][nt], pa[0][0], pa[0][1], pa[0][2], pa[0][3], b0, b1);
                mma_tf32(o[1][nt], pa[1][0], pa[1][1], pa[1][2], pa[1][3], b0, b1);
            }
        }
    }

#pragma unroll
    for (int mi = 0; mi < 2; mi++) {
        float ivA = 1.0f / lrow[mi][0], ivB = 1.0f / lrow[mi][1];
        int qA = qt * 128 + wrow + mi * 16 + gid;
        int qB = qA + 8;
#pragma unroll
        for (int nt = 0; nt < 8; nt++) {
            *(float2*)(out + ((size_t)(b * S_ + qA)) * HID_ + h * HD_ + nt * 8 + (tig << 1)) =
                make_float2(o[mi][nt][0] * ivA, o[mi][nt][1] * ivA);
            *(float2*)(out + ((size_t)(b * S_ + qB)) * HID_ + h * HD_ + nt * 8 + (tig << 1)) =
                make_float2(o[mi][nt][2] * ivB, o[mi][nt][3] * ivB);
        }
    }
}

// ---------------- launch: fork independent producers into parallel graph branches ----------------
extern "C" void kernel_launch(void* const* d_in, const int* in_sizes, int n_in,
                              void* d_out, int out_size) {
    const float* qhs   = nullptr;
    const float* kvh   = nullptr;
    const float* embx  = nullptr;
    const float* ru    = nullptr;
    const float* Wkv_w = nullptr;
    const float* Wkv_b = nullptr;
    for (int i = 0; i < n_in; i++) {
        int sz = in_sizes[i];
        if (sz == B_ * S_ * HID_) {
            if (!qhs) qhs = (const float*)d_in[i];
            else if (!kvh) kvh = (const float*)d_in[i];
        } else if (sz == B_ * E_ * HID_) {
            embx = (const float*)d_in[i];
        } else if (sz == B_ * S_ * S_) {
            ru = (const float*)d_in[i];
        } else if (sz == 2 * HID_ * HID_) {
            Wkv_w = (const float*)d_in[i];
        } else if (sz == 2 * HID_) {
            Wkv_b = (const float*)d_in[i];
        }
        // Wq_w / Wq_b / attention_mask unused by the reference math.
    }
    float* out = (float*)d_out;

    const int FLASH_SMEM = SM_TOTF * (int)sizeof(float);   // 110,592 B
    static bool attr_set = false;
    if (!attr_set) {
        cudaFuncSetAttribute(flash_kernel, cudaFuncAttributeMaxDynamicSharedMemorySize, FLASH_SMEM);
        attr_set = true;
    }

    cudaStream_t s1, s2;
    cudaStreamCreateWithFlags(&s1, cudaStreamNonBlocking);
    cudaStreamCreateWithFlags(&s2, cudaStreamNonBlocking);
    cudaEvent_t eFork, eTable, eMask, eQrope;
    cudaEventCreateWithFlags(&eFork,  cudaEventDisableTiming);
    cudaEventCreateWithFlags(&eTable, cudaEventDisableTiming);
    cudaEventCreateWithFlags(&eMask,  cudaEventDisableTiming);
    cudaEventCreateWithFlags(&eQrope, cudaEventDisableTiming);

    // fork point on the capture (legacy) stream
    cudaEventRecord(eFork, 0);

    // branch s1: mask (independent of everything)
    cudaStreamWaitEvent(s1, eFork, 0);
    int maskWarps = B_ * S_ * WPR;
    mask_kernel<<<(maskWarps * 32 + 255) / 256, 256, 0, s1>>>(ru);
    cudaEventRecord(eMask, s1);

    // main stream: rope table -> prepack -> kv_gemm (critical path)
    rope_table_kernel<<<(L_ * 32 + 255) / 256, 256>>>();
    cudaEventRecord(eTable, 0);

    // branch s2: qrope (needs rope table only)
    cudaStreamWaitEvent(s2, eTable, 0);
    int qN = B_ * S_ * NH_ * 32;
    qrope_kernel<<<(qN + 255) / 256, 256, 0, s2>>>(qhs);
    cudaEventRecord(eQrope, s2);

    const int PREP_N = M_PAD * (HID_ / 4) + 2 * HID_ * (HID_ / 4);
    prepack_kernel<<<(PREP_N + 255) / 256, 256>>>(embx, kvh, Wkv_w);

    kv_gemm_tc<<<dim3(12, 33), 256>>>(Wkv_b);

    // join: flash needs mask + qrope + kv outputs
    cudaStreamWaitEvent(0, eMask, 0);
    cudaStreamWaitEvent(0, eQrope, 0);
    flash_kernel<<<dim3(S_ / 128, NH_, B_), 128, FLASH_SMEM>>>(out);

    cudaEventDestroy(eFork);
    cudaEventDestroy(eTable);
    cudaEventDestroy(eMask);
    cudaEventDestroy(eQrope);
    cudaStreamDestroy(s1);
    cudaStreamDestroy(s2);
}

// round 16
// speedup vs baseline: 1.0784x; 1.0784x over previous
#include <cuda_runtime.h>
#include <math.h>

#define B_    2
#define S_    2048
#define E_    8
#define HID_  768
#define NH_   12
#define HD_   64
#define L_    2056           // E + S
#define M_ROWS 4112          // B * L
#define M_PAD  4224          // 33 * 128 (padded rows for prepacked X)
#define WPR   66             // mask words per q-row
#define NEG_  (-10000.0f)
#define NSPLIT 3
#define JT_PER 11            // 33 kv tiles / 3 splits
#define ROWS_BH (B_ * NH_ * S_)   // 49152 partial rows per split

// -ln(10000)/64 in fp32
#define RC_ (-1.4391157031059265e-01f)

// ---------------- scratch ----------------
__device__ __align__(16) float    g_qr[B_ * NH_ * S_ * HD_];   // [b][h][s][d], 1/8-scaled, tf32-rounded
__device__ __align__(16) float    g_kt[B_ * NH_ * HD_ * L_];   // [b][h][d][pos], tf32-rounded
__device__ __align__(16) float    g_v [B_ * NH_ * L_ * HD_];   // [b][h][pos][d], tf32-rounded
__device__           unsigned     g_mask[B_ * S_ * WPR];       // packed enh bits
__device__ __align__(16) float    g_xr[M_PAD * HID_];          // prepacked tf32-rounded X rows
__device__ __align__(16) float    g_wr[2 * HID_ * HID_];       // prepacked tf32-rounded W
__device__ __align__(8)  float    g_sv[L_ * 32];               // sinvec[pos][j]
__device__ __align__(8)  float    g_cv[L_ * 32];               // cosvec[pos][j]
__device__ __align__(16) float    g_po[NSPLIT * ROWS_BH * HD_]; // partial O (unnormalized)
__device__           float        g_pm[NSPLIT * ROWS_BH];       // partial m
__device__           float        g_pl[NSPLIT * ROWS_BH];       // partial l

// ---------------- helpers ----------------
__device__ __forceinline__ float tf32r(float x) {
    unsigned u;
    asm("cvt.rna.tf32.f32 %0, %1;" : "=r"(u) : "f"(x));
    return __uint_as_float(u);
}

__device__ __forceinline__ void mma_tf32(float* d,
                                         unsigned a0, unsigned a1, unsigned a2, unsigned a3,
                                         unsigned b0, unsigned b1) {
    asm volatile(
        "mma.sync.aligned.m16n8k8.row.col.f32.tf32.tf32.f32 "
        "{%0,%1,%2,%3}, {%4,%5,%6,%7}, {%8,%9}, {%0,%1,%2,%3};"
        : "+f"(d[0]), "+f"(d[1]), "+f"(d[2]), "+f"(d[3])
        : "r"(a0), "r"(a1), "r"(a2), "r"(a3), "r"(b0), "r"(b1));
}

__device__ __forceinline__ void cpa16(unsigned dst, const void* src, unsigned sz) {
    asm volatile("cp.async.cg.shared.global [%0], [%1], 16, %2;"
                 :: "r"(dst), "l"(src), "r"(sz));
}
__device__ __forceinline__ void cpa16u(unsigned dst, const void* src) {
    asm volatile("cp.async.cg.shared.global [%0], [%1], 16;"
                 :: "r"(dst), "l"(src));
}

// ---------------- kernel 0a: rope table ----------------
__global__ void rope_table_kernel() {
    int idx = blockIdx.x * blockDim.x + threadIdx.x;
    if (idx >= L_ * 32) return;
    int j = idx & 31;
    int pos = idx >> 5;
    int i = j >> 1;
    float da = expf((float)(2 * i) * RC_);
    float db = expf((float)(2 * (16 + i)) * RC_);
    float aa = (float)pos * da, ab = (float)pos * db;
    g_sv[idx] = (j & 1) ? cosf(aa) : sinf(aa);
    g_cv[idx] = (j & 1) ? cosf(ab) : sinf(ab);
}

// ---------------- kernel 0b: prepack X (merged, padded) and W, tf32-rounded ----------------
__global__ void prepack_kernel(const float* __restrict__ embx, const float* __restrict__ kvh,
                               const float* __restrict__ W) {
    const int XN = M_PAD * (HID_ / 4);            // float4 count for X
    const int WN = 2 * HID_ * (HID_ / 4);
    int idx = blockIdx.x * blockDim.x + threadIdx.x;
    if (idx < XN) {
        int m = idx / (HID_ / 4);
        int c4 = (idx % (HID_ / 4)) * 4;
        float4 v = make_float4(0.f, 0.f, 0.f, 0.f);
        if (m < M_ROWS) {
            int b = m / L_, pos = m % L_;
            const float* src = (pos < E_) ? embx + ((size_t)(b * E_ + pos)) * HID_
                                          : kvh  + ((size_t)(b * S_ + (pos - E_))) * HID_;
            v = *(const float4*)(src + c4);
        }
        v.x = tf32r(v.x); v.y = tf32r(v.y); v.z = tf32r(v.z); v.w = tf32r(v.w);
        *(float4*)&g_xr[(size_t)m * HID_ + c4] = v;
    } else if (idx < XN + WN) {
        int k = idx - XN;
        float4 v = *(const float4*)(W + (size_t)k * 4);
        v.x = tf32r(v.x); v.y = tf32r(v.y); v.z = tf32r(v.z); v.w = tf32r(v.w);
        *(float4*)&g_wr[(size_t)k * 4] = v;
    }
}

// ---------------- kernel 1: mask pack ----------------
__global__ void mask_kernel(const float* __restrict__ ru) {
    int gw = (blockIdx.x * blockDim.x + threadIdx.x) >> 5;
    int lane = threadIdx.x & 31;
    if (gw >= B_ * S_ * WPR) return;
    int w = gw % WPR;
    int q = (gw / WPR) % S_;
    int b = gw / (WPR * S_);
    int j = w * 32 + lane;
    bool ok = false;
    if (j < L_) {
        if (j < E_) ok = true;
        else {
            int si = j - E_;
            ok = (ru[((size_t)b * S_ + q) * S_ + si] >= 0.1f) && (si != q);
        }
    }
    unsigned bits = __ballot_sync(0xffffffffu, ok);
    if (lane == 0) g_mask[gw] = bits;
}

// ---------------- kernel 2: Q rope (table lookup) ----------------
__global__ void qrope_kernel(const float* __restrict__ qhs) {
    int idx = blockIdx.x * blockDim.x + threadIdx.x;
    if (idx >= B_ * S_ * NH_ * 32) return;
    int j = idx & 31;
    int h = (idx >> 5) % NH_;
    int s = (idx / (32 * NH_)) % S_;
    int b = idx / (32 * NH_ * S_);
    const float* src = qhs + ((size_t)(b * S_ + s)) * HID_ + h * HD_ + 2 * j;
    float x0 = src[0], x1 = src[1];
    float sv = g_sv[s * 32 + j];
    float cv = g_cv[s * 32 + j];
    float o0 = -x1 * cv * 0.125f;
    float o1 =  x0 * sv * 0.125f;
    float* dst = g_qr + ((size_t)(b * NH_ + h) * S_ + s) * HD_ + 2 * j;
    dst[0] = tf32r(o0);
    dst[1] = tf32r(o1);
}

// ---------------- kernel 3: tf32 KV GEMM, cp.async double-buffered ----------------
#define GSTR 36
#define ABUF (128 * GSTR)                 // floats per buffer (4608)
__global__ __launch_bounds__(256, 2) void kv_gemm_tc(const float* __restrict__ bias) {
    __shared__ float As[2 * ABUF];
    __shared__ float Ws[2 * ABUF];
    unsigned sbA = (unsigned)__cvta_generic_to_shared(As);
    unsigned sbW = (unsigned)__cvta_generic_to_shared(Ws);
    int nb = blockIdx.x;
    int mt = blockIdx.y;
    int tid = threadIdx.x;
    int warp = tid >> 5, lane = tid & 31;
    int wm = warp >> 2, wn = warp & 3;
    int gid = lane >> 2, tig = lane & 3;

    float acc[4][4][4];
#pragma unroll
    for (int mi = 0; mi < 4; mi++)
#pragma unroll
        for (int ni = 0; ni < 4; ni++)
#pragma unroll
            for (int k = 0; k < 4; k++) acc[mi][ni][k] = 0.f;

    int lr  = tid >> 3;
    int lk4 = (tid & 7) << 2;
    const float* xbase = g_xr + (size_t)(mt * 128) * HID_;
    const float* wbase = g_wr + (size_t)(nb * 128) * HID_;

#pragma unroll
    for (int it = 0; it < 4; it++) {
        int r = lr + it * 32;
        cpa16u(sbA + (r * GSTR + lk4) * 4, xbase + (size_t)r * HID_ + lk4);
        cpa16u(sbW + (r * GSTR + lk4) * 4, wbase + (size_t)r * HID_ + lk4);
    }
    asm volatile("cp.async.commit_group;");

    for (int c = 0; c < 24; c++) {
        int cur = c & 1;
        if (c + 1 < 24) {
            int nxt = (c + 1) & 1;
            int k0 = (c + 1) * 32;
#pragma unroll
            for (int it = 0; it < 4; it++) {
                int r = lr + it * 32;
                cpa16u(sbA + (nxt * ABUF + r * GSTR + lk4) * 4, xbase + (size_t)r * HID_ + k0 + lk4);
                cpa16u(sbW + (nxt * ABUF + r * GSTR + lk4) * 4, wbase + (size_t)r * HID_ + k0 + lk4);
            }
            asm volatile("cp.async.commit_group;");
            asm volatile("cp.async.wait_group 1;");
        } else {
            asm volatile("cp.async.wait_group 0;");
        }
        __syncthreads();

        const float* Ab = As + cur * ABUF;
        const float* Wb = Ws + cur * ABUF;
#pragma unroll
        for (int kt = 0; kt < 4; kt++) {
            unsigned a[4][4];
#pragma unroll
            for (int mi = 0; mi < 4; mi++) {
                int rA = wm * 64 + mi * 16 + gid;
                a[mi][0] = __float_as_uint(Ab[rA * GSTR + kt * 8 + tig]);
                a[mi][1] = __float_as_uint(Ab[(rA + 8) * GSTR + kt * 8 + tig]);
                a[mi][2] = __float_as_uint(Ab[rA * GSTR + kt * 8 + tig + 4]);
                a[mi][3] = __float_as_uint(Ab[(rA + 8) * GSTR + kt * 8 + tig + 4]);
            }
#pragma unroll
            for (int ni = 0; ni < 4; ni++) {
                int n = wn * 32 + ni * 8 + gid;
                unsigned b0 = __float_as_uint(Wb[n * GSTR + kt * 8 + tig]);
                unsigned b1 = __float_as_uint(Wb[n * GSTR + kt * 8 + tig + 4]);
#pragma unroll
                for (int mi = 0; mi < 4; mi++)
                    mma_tf32(acc[mi][ni], a[mi][0], a[mi][1], a[mi][2], a[mi][3], b0, b1);
            }
        }
        __syncthreads();
    }

    bool isV = (nb >= 6);
#pragma unroll
    for (int ni = 0; ni < 4; ni++) {
        int c = nb * 128 + wn * 32 + ni * 8 + tig * 2;
        float bv0 = bias[c], bv1 = bias[c + 1];
        if (isV) {
            int vcol = c - 768;
            int h = vcol >> 6, d = vcol & 63;
#pragma unroll
            for (int mi = 0; mi < 4; mi++) {
                int mA = mt * 128 + wm * 64 + mi * 16 + gid;
                int mB = mA + 8;
                if (mA < M_ROWS) {
                    int bb = mA / L_, pos = mA % L_;
                    *(float2*)&g_v[(((size_t)(bb * NH_ + h)) * L_ + pos) * HD_ + d] =
                        make_float2(tf32r(acc[mi][ni][0] + bv0), tf32r(acc[mi][ni][1] + bv1));
                }
                if (mB < M_ROWS) {
                    int bb = mB / L_, pos = mB % L_;
                    *(float2*)&g_v[(((size_t)(bb * NH_ + h)) * L_ + pos) * HD_ + d] =
                        make_float2(tf32r(acc[mi][ni][2] + bv0), tf32r(acc[mi][ni][3] + bv1));
                }
            }
        } else {
            int h = c >> 6, d = c & 63;          // d even
            int j = d >> 1;
#pragma unroll
            for (int mi = 0; mi < 4; mi++) {
#pragma unroll
                for (int half = 0; half < 2; half++) {
                    int m = mt * 128 + wm * 64 + mi * 16 + gid + half * 8;
                    if (m >= M_ROWS) continue;
                    int bb = m / L_, pos = m % L_;
                    float sv = g_sv[pos * 32 + j];
                    float cv = g_cv[pos * 32 + j];
                    float x0 = acc[mi][ni][half * 2 + 0] + bv0;
                    float x1 = acc[mi][ni][half * 2 + 1] + bv1;
                    float* base = g_kt + ((size_t)(bb * NH_ + h) * HD_ + d) * L_ + pos;
                    base[0]  = tf32r(-x1 * cv);
                    base[L_] = tf32r( x0 * sv);
                }
            }
        }
    }
}

// ---------------- kernel 4: split-KV flash attention ----------------
#define QP_STR 72
#define KV_STR 72
#define SM_PS  0
#define SM_K0  (128 * QP_STR)
#define SM_K1  (SM_K0 + 64 * KV_STR)
#define SM_V0  (SM_K1 + 64 * KV_STR)
#define SM_V1  (SM_V0 + 64 * KV_STR)
#define SM_TOTF (SM_V1 + 64 * KV_STR)  // 27648 floats = 110592 B

__global__ __launch_bounds__(128, 2) void flash_kernel() {
    extern __shared__ float sm[];
    float* Ps = sm + SM_PS;
    unsigned sbase = (unsigned)__cvta_generic_to_shared(sm);

    int qt = blockIdx.x, h = blockIdx.y;
    int b = blockIdx.z / NSPLIT, split = blockIdx.z % NSPLIT;
    int jt0 = split * JT_PER;
    int tid = threadIdx.x;
    int warp = tid >> 5, lane = tid & 31;
    int gid = lane >> 2, tig = lane & 3;
    int wrow = warp * 32;

    const float* ktb = g_kt + (size_t)(b * NH_ + h) * HD_ * L_;
    const float* vb  = g_v  + (size_t)(b * NH_ + h) * L_ * HD_;
    const unsigned* mbg = g_mask + (size_t)(b * S_ + qt * 128) * WPR;

    const float* qbase = g_qr + ((size_t)(b * NH_ + h) * S_ + qt * 128) * HD_;
#pragma unroll
    for (int j = 0; j < 16; j++) {
        int c = lane + j * 32;
        int r = wrow + (c >> 4);
        int cc = (c & 15) << 2;
        float4 v = *(const float4*)(qbase + r * 64 + cc);
        float* q = Ps + r * QP_STR + cc;
        q[0] = v.x; q[1] = v.y; q[2] = v.z; q[3] = v.w;
    }
    __syncwarp();
    unsigned qa[2][8][4];
#pragma unroll
    for (int mi = 0; mi < 2; mi++) {
        int rA = wrow + mi * 16 + gid, rB = rA + 8;
#pragma unroll
        for (int kt = 0; kt < 8; kt++) {
            qa[mi][kt][0] = __float_as_uint(Ps[rA * QP_STR + kt * 8 + tig]);
            qa[mi][kt][1] = __float_as_uint(Ps[rB * QP_STR + kt * 8 + tig]);
            qa[mi][kt][2] = __float_as_uint(Ps[rA * QP_STR + kt * 8 + tig + 4]);
            qa[mi][kt][3] = __float_as_uint(Ps[rB * QP_STR + kt * 8 + tig + 4]);
        }
    }
    __syncwarp();

    float o[2][8][4];
#pragma unroll
    for (int mi = 0; mi < 2; mi++)
#pragma unroll
        for (int nt = 0; nt < 8; nt++)
#pragma unroll
            for (int k = 0; k < 4; k++) o[mi][nt][k] = 0.f;
    float mrow[2][2], lrow[2][2];
#pragma unroll
    for (int mi = 0; mi < 2; mi++) { mrow[mi][0] = mrow[mi][1] = -1e30f; lrow[mi][0] = lrow[mi][1] = 0.f; }

    {
        int pbase = jt0 * 64;
#pragma unroll
        for (int i = 0; i < 8; i++) {
            int c = tid + i * 128;
            int d = c >> 4, p4 = (c & 15) << 2;
            unsigned dst = sbase + (SM_K0 + d * KV_STR + p4) * 4;
            cpa16(dst, ktb + (size_t)d * L_ + pbase + p4, (pbase + p4 + 4 <= L_) ? 16u : 0u);
        }
#pragma unroll
        for (int i = 0; i < 8; i++) {
            int c = tid + i * 128;
            int pos = c >> 4, d4 = (c & 15) << 2;
            unsigned dst = sbase + (SM_V0 + pos * KV_STR + d4) * 4;
            cpa16(dst, vb + (size_t)(pbase + pos) * HD_ + d4, (pbase + pos < L_) ? 16u : 0u);
        }
        asm volatile("cp.async.commit_group;");
    }

    for (int t = 0; t < JT_PER; t++) {
        int jt = jt0 + t;
        int cur = t & 1;
        asm volatile("cp.async.wait_group 0;");
        __syncthreads();
        if (t + 1 < JT_PER) {
            int pbase = (jt + 1) * 64;
            int kb = cur ? SM_K0 : SM_K1;
            int vbuf = cur ? SM_V0 : SM_V1;
#pragma unroll
            for (int i = 0; i < 8; i++) {
                int c = tid + i * 128;
                int d = c >> 4, p4 = (c & 15) << 2;
                unsigned dst = sbase + (kb + d * KV_STR + p4) * 4;
                cpa16(dst, ktb + (size_t)d * L_ + pbase + p4, (pbase + p4 + 4 <= L_) ? 16u : 0u);
            }
#pragma unroll
            for (int i = 0; i < 8; i++) {
                int c = tid + i * 128;
                int pos = c >> 4, d4 = (c & 15) << 2;
                unsigned dst = sbase + (vbuf + pos * KV_STR + d4) * 4;
                cpa16(dst, vb + (size_t)(pbase + pos) * HD_ + d4, (pbase + pos < L_) ? 16u : 0u);
            }
            asm volatile("cp.async.commit_group;");
        }

        unsigned mw[2][2][2];
#pragma unroll
        for (int mi = 0; mi < 2; mi++)
#pragma unroll
            for (int hf = 0; hf < 2; hf++) {
                int r = wrow + mi * 16 + gid + hf * 8;
                mw[mi][hf][0] = mbg[(size_t)r * WPR + jt * 2];
                mw[mi][hf][1] = mbg[(size_t)r * WPR + jt * 2 + 1];
            }

        float sf[2][8][4];
#pragma unroll
        for (int mi = 0; mi < 2; mi++)
#pragma unroll
            for (int nt = 0; nt < 8; nt++) {
                unsigned wA = (nt < 4) ? mw[mi][0][0] : mw[mi][0][1];
                unsigned wB = (nt < 4) ? mw[mi][1][0] : mw[mi][1][1];
                int s0 = ((nt & 3) << 3) + (tig << 1);
                sf[mi][nt][0] = ((wA >> s0) & 1u) ? 0.f : NEG_;
                sf[mi][nt][1] = ((wA >> (s0 + 1)) & 1u) ? 0.f : NEG_;
                sf[mi][nt][2] = ((wB >> s0) & 1u) ? 0.f : NEG_;
                sf[mi][nt][3] = ((wB >> (s0 + 1)) & 1u) ? 0.f : NEG_;
            }

        const float* Kb = sm + (cur ? SM_K1 : SM_K0);
#pragma unroll
        for (int kt = 0; kt < 8; kt++) {
#pragma unroll
            for (int nt = 0; nt < 8; nt++) {
                unsigned b0 = __float_as_uint(Kb[(kt * 8 + tig) * KV_STR + nt * 8 + gid]);
                unsigned b1 = __float_as_uint(Kb[(kt * 8 + tig + 4) * KV_STR + nt * 8 + gid]);
                mma_tf32(sf[0][nt], qa[0][kt][0], qa[0][kt][1], qa[0][kt][2], qa[0][kt][3], b0, b1);
                mma_tf32(sf[1][nt], qa[1][kt][0], qa[1][kt][1], qa[1][kt][2], qa[1][kt][3], b0, b1);
            }
        }

#pragma unroll
        for (int mi = 0; mi < 2; mi++) {
            int rA = wrow + mi * 16 + gid, rB = rA + 8;
            float mxA = -1e30f, mxB = -1e30f;
#pragma unroll
            for (int nt = 0; nt < 8; nt++) {
                mxA = fmaxf(mxA, fmaxf(sf[mi][nt][0], sf[mi][nt][1]));
                mxB = fmaxf(mxB, fmaxf(sf[mi][nt][2], sf[mi][nt][3]));
            }
            mxA = fmaxf(mxA, __shfl_xor_sync(0xffffffffu, mxA, 1));
            mxA = fmaxf(mxA, __shfl_xor_sync(0xffffffffu, mxA, 2));
            mxB = fmaxf(mxB, __shfl_xor_sync(0xffffffffu, mxB, 1));
            mxB = fmaxf(mxB, __shfl_xor_sync(0xffffffffu, mxB, 2));
            float mnA = fmaxf(mrow[mi][0], mxA), mnB = fmaxf(mrow[mi][1], mxB);
            float alA = __expf(mrow[mi][0] - mnA), alB = __expf(mrow[mi][1] - mnB);
            float lsA = 0.f, lsB = 0.f;
#pragma unroll
            for (int nt = 0; nt < 8; nt++) {
                float p0 = tf32r(__expf(sf[mi][nt][0] - mnA));
                float p1 = tf32r(__expf(sf[mi][nt][1] - mnA));
                float p2 = tf32r(__expf(sf[mi][nt][2] - mnB));
                float p3 = tf32r(__expf(sf[mi][nt][3] - mnB));
                lsA += p0 + p1; lsB += p2 + p3;
                *(float2*)(Ps + rA * QP_STR + nt * 8 + (tig << 1)) = make_float2(p0, p1);
                *(float2*)(Ps + rB * QP_STR + nt * 8 + (tig << 1)) = make_float2(p2, p3);
            }
            lsA += __shfl_xor_sync(0xffffffffu, lsA, 1);
            lsA += __shfl_xor_sync(0xffffffffu, lsA, 2);
            lsB += __shfl_xor_sync(0xffffffffu, lsB, 1);
            lsB += __shfl_xor_sync(0xffffffffu, lsB, 2);
            lrow[mi][0] = lrow[mi][0] * alA + lsA; mrow[mi][0] = mnA;
            lrow[mi][1] = lrow[mi][1] * alB + lsB; mrow[mi][1] = mnB;
#pragma unroll
            for (int nt = 0; nt < 8; nt++) {
                o[mi][nt][0] *= alA; o[mi][nt][1] *= alA;
                o[mi][nt][2] *= alB; o[mi][nt][3] *= alB;
            }
        }
        __syncwarp();

        const float* Vb = sm + (cur ? SM_V1 : SM_V0);
#pragma unroll
        for (int kt = 0; kt < 8; kt++) {
            unsigned pa[2][4];
#pragma unroll
            for (int mi = 0; mi < 2; mi++) {
                int rA = wrow + mi * 16 + gid, rB = rA + 8;
                pa[mi][0] = __float_as_uint(Ps[rA * QP_STR + kt * 8 + tig]);
                pa[mi][1] = __float_as_uint(Ps[rB * QP_STR + kt * 8 + tig]);
                pa[mi][2] = __float_as_uint(Ps[rA * QP_STR + kt * 8 + tig + 4]);
                pa[mi][3] = __float_as_uint(Ps[rB * QP_STR + kt * 8 + tig + 4]);
            }
#pragma unroll
            for (int nt = 0; nt < 8; nt++) {
                unsigned b0 = __float_as_uint(Vb[(kt * 8 + tig) * KV_STR + nt * 8 + gid]);
                unsigned b1 = __float_as_uint(Vb[(kt * 8 + tig + 4) * KV_STR + nt * 8 + gid]);
                mma_tf32(o[0][nt], pa[0][0], pa[0][1], pa[0][2], pa[0][3], b0, b1);
                mma_tf32(o[1][nt], pa[1][0], pa[1][1], pa[1][2], pa[1][3], b0, b1);
            }
        }
    }

    // ---- epilogue: write partial (unnormalized O, m, l) ----
    size_t prow0 = ((size_t)(split * B_ + b) * NH_ + h) * S_ + qt * 128;
    float* pob = g_po + prow0 * HD_;
#pragma unroll
    for (int mi = 0; mi < 2; mi++) {
        int rA = wrow + mi * 16 + gid, rB = rA + 8;
#pragma unroll
        for (int nt = 0; nt < 8; nt++) {
            *(float2*)(pob + (size_t)rA * HD_ + nt * 8 + (tig << 1)) =
                make_float2(o[mi][nt][0], o[mi][nt][1]);
            *(float2*)(pob + (size_t)rB * HD_ + nt * 8 + (tig << 1)) =
                make_float2(o[mi][nt][2], o[mi][nt][3]);
        }
        if (tig == 0) {
            g_pm[prow0 + rA] = mrow[mi][0];
            g_pl[prow0 + rA] = lrow[mi][0];
            g_pm[prow0 + rB] = mrow[mi][1];
            g_pl[prow0 + rB] = lrow[mi][1];
        }
    }
}

// ---------------- kernel 5: split merge ----------------
__global__ void merge_kernel(float* __restrict__ out) {
    int idx = blockIdx.x * blockDim.x + threadIdx.x;
    if (idx >= ROWS_BH * 16) return;
    int c4 = (idx & 15) << 2;
    int row = idx >> 4;                  // (b*NH + h)*S + q
    int q = row % S_;
    int bh = row / S_;
    int h = bh % NH_;
    int b = bh / NH_;

    float m0 = g_pm[row];
    float m1 = g_pm[ROWS_BH + row];
    float m2 = g_pm[2 * ROWS_BH + row];
    float ms = fmaxf(m0, fmaxf(m1, m2));
    float w0 = __expf(m0 - ms), w1 = __expf(m1 - ms), w2 = __expf(m2 - ms);
    float l = g_pl[row] * w0 + g_pl[ROWS_BH + row] * w1 + g_pl[2 * ROWS_BH + row] * w2;

    float4 a0 = *(const float4*)(g_po + ((size_t)row) * HD_ + c4);
    float4 a1 = *(const float4*)(g_po + ((size_t)(ROWS_BH) + row) * HD_ + c4);
    float4 a2 = *(const float4*)(g_po + ((size_t)(2 * ROWS_BH) + row) * HD_ + c4);
    float inv = 1.0f / l;
    float4 r;
    r.x = (a0.x * w0 + a1.x * w1 + a2.x * w2) * inv;
    r.y = (a0.y * w0 + a1.y * w1 + a2.y * w2) * inv;
    r.z = (a0.z * w0 + a1.z * w1 + a2.z * w2) * inv;
    r.w = (a0.w * w0 + a1.w * w1 + a2.w * w2) * inv;
    *(float4*)(out + ((size_t)(b * S_ + q)) * HID_ + h * HD_ + c4) = r;
}

// ---------------- launch ----------------
extern "C" void kernel_launch(void* const* d_in, const int* in_sizes, int n_in,
                              void* d_out, int out_size) {
    const float* qhs   = nullptr;
    const float* kvh   = nullptr;
    const float* embx  = nullptr;
    const float* ru    = nullptr;
    const float* Wkv_w = nullptr;
    const float* Wkv_b = nullptr;
    for (int i = 0; i < n_in; i++) {
        int sz = in_sizes[i];
        if (sz == B_ * S_ * HID_) {
            if (!qhs) qhs = (const float*)d_in[i];
            else if (!kvh) kvh = (const float*)d_in[i];
        } else if (sz == B_ * E_ * HID_) {
            embx = (const float*)d_in[i];
        } else if (sz == B_ * S_ * S_) {
            ru = (const float*)d_in[i];
        } else if (sz == 2 * HID_ * HID_) {
            Wkv_w = (const float*)d_in[i];
        } else if (sz == 2 * HID_) {
            Wkv_b = (const float*)d_in[i];
        }
        // Wq_w / Wq_b / attention_mask unused by the reference math.
    }
    float* out = (float*)d_out;

    rope_table_kernel<<<(L_ * 32 + 255) / 256, 256>>>();

    const int PREP_N = M_PAD * (HID_ / 4) + 2 * HID_ * (HID_ / 4);
    prepack_kernel<<<(PREP_N + 255) / 256, 256>>>(embx, kvh, Wkv_w);

    int maskWarps = B_ * S_ * WPR;
    mask_kernel<<<(maskWarps * 32 + 255) / 256, 256>>>(ru);

    int qN = B_ * S_ * NH_ * 32;
    qrope_kernel<<<(qN + 255) / 256, 256>>>(qhs);

    kv_gemm_tc<<<dim3(12, 33), 256>>>(Wkv_b);

    const int FLASH_SMEM = SM_TOTF * (int)sizeof(float);   // 110,592 B
    cudaFuncSetAttribute(flash_kernel, cudaFuncAttributeMaxDynamicSharedMemorySize, FLASH_SMEM);
    flash_kernel<<<dim3(S_ / 128, NH_, B_ * NSPLIT), 128, FLASH_SMEM>>>();

    int mergeN = ROWS_BH * 16;
    merge_kernel<<<(mergeN + 255) / 256, 256>>>(out);
}